// round 9
// baseline (speedup 1.0000x reference)
#include <cuda_runtime.h>
#include <cuda_bf16.h>
#include <math.h>

#define KC 64
#define DD 128
#define NN 4096
#define NB 32
#define NT 512
#define GRID (NN / NB)   // 128 blocks: one per SM, single balanced wave
#define MPAD 129

#define LN2F 0.6931471805599453f
#define LOG2PIF 1.8378770664093453f
#define LGAMMA64F 201.00931639928152f

// ---------------- device scratch (zero-init; self-resetting each run) ----------------
__device__ float g_counts[KC];
__device__ float g_numer[KC * KC];
__device__ float g_rank;
__device__ float g_js;
__device__ int   g_arrive;
__device__ int   g_done;

__device__ __forceinline__ float softplus_precise(float x) {
    return (x > 0.0f) ? (x + log1pf(expf(-x))) : log1pf(expf(x));
}
__device__ __forceinline__ float A_of(float kap) {
    float kc = fmaxf(kap, 1e-8f);
    return (kc > 50.0f) ? (1.0f - 127.0f / (2.0f * kc)) : (kc / 128.0f);
}

struct Smem {
    float mus[KC * MPAD];        // raw mus, padded (33KB) — live through epilogue
    float f[NB][DD];             // features (16KB) — epilogue scratch after mainloop
    float L[NB][KC];             // logits (8KB)    — epilogue scratch after mainloop
    float invn[NB];
    float invmu[KC], kap[KC], lc[KC];
    float musq[8][KC];
    int   lab[NB];
    int   cnt_sh;
};

__global__ void __launch_bounds__(NT) k_fused(const float* __restrict__ feat,
                                              const float* __restrict__ musp,
                                              const float* __restrict__ rho,
                                              const int* __restrict__ lab32,
                                              float* __restrict__ out) {
    extern __shared__ char smem_raw[];
    Smem* s = (Smem*)smem_raw;
    int tid = threadIdx.x;
    int bid = blockIdx.x;
    int n0 = bid * NB;

    // labels dtype probe (odd int32 words nonzero => int32 labels)
    int pred = (lab32[2 * tid + 1] != 0);

    // load mus_param coalesced -> padded rows
    {
        const float4* msrc = (const float4*)musp;
#pragma unroll
        for (int r = 0; r < 4; r++) {
            int idx = tid + NT * r;
            float4 v = msrc[idx];
            int k = idx >> 5, d = (idx & 31) * 4;
            float* p = &s->mus[k * MPAD + d];
            p[0] = v.x; p[1] = v.y; p[2] = v.z; p[3] = v.w;
        }
    }
    // load 32x128 features
    {
        const float4* src = (const float4*)(feat + n0 * DD);
        float4* dst = (float4*)&s->f[0][0];
        dst[tid]      = src[tid];
        dst[tid + NT] = src[tid + NT];
    }
    int anyodd = __syncthreads_or(pred);
    int shift = anyodd ? 0 : 1;

    if (tid < NB) {
        int l = lab32[(n0 + tid) << shift];
        s->lab[tid] = min(max(l, 0), KC - 1);
    }

    // mus squared-norm partials
    {
        int k = tid & 63, q = tid >> 6;
        float sm = 0.0f;
        const float* p = &s->mus[k * MPAD + q * 16];
#pragma unroll
        for (int r = 0; r < 16; r++) { float m = p[r]; sm += m * m; }
        s->musq[q][k] = sm;
    }
    // feature norms
    {
        int w = tid >> 5, lane = tid & 31;
#pragma unroll
        for (int rr = 0; rr < 2; rr++) {
            int r = 2 * w + rr;
            float sm = 0.0f;
#pragma unroll
            for (int c = 0; c < 4; c++) {
                float x = s->f[r][lane + 32 * c];
                sm += x * x;
            }
#pragma unroll
            for (int o = 16; o > 0; o >>= 1) sm += __shfl_xor_sync(0xffffffffu, sm, o);
            if (lane == 0) s->invn[r] = 1.0f / fmaxf(sqrtf(sm), 1e-12f);
        }
    }
    __syncthreads();

    // per-class scalars
    if (tid < KC) {
        float sm = 0.0f;
#pragma unroll
        for (int q = 0; q < 8; q++) sm += s->musq[q][tid];
        s->invmu[tid] = 1.0f / fmaxf(sqrtf(sm), 1e-12f);
        float r = rho[tid];
        float kap = fmaxf(softplus_precise(r), 1e-6f);
        s->kap[tid] = kap;
        float logI = (kap < 1e-3f)
                   ? 63.0f * logf(kap * 0.5f + 1e-12f) - LGAMMA64F
                   : kap - 0.5f * logf(6.283185307179586f * kap + 1e-12f);
        s->lc[tid] = -63.0f * logf(kap + 1e-12f) - 64.0f * LOG2PIF - logI;
    }
    if (tid < NB) atomicAdd(&g_counts[s->lab[tid]], 1.0f);
    __syncthreads();

    // L = logC + kappa*invmu*invn*(f . mu_raw); 8 groups x 4 samples
    int g = tid >> 6;
    int k = tid & 63;
    {
        float acc0 = 0.f, acc1 = 0.f, acc2 = 0.f, acc3 = 0.f;
        const float4* f0 = (const float4*)&s->f[g * 4 + 0][0];
        const float4* f1 = (const float4*)&s->f[g * 4 + 1][0];
        const float4* f2 = (const float4*)&s->f[g * 4 + 2][0];
        const float4* f3 = (const float4*)&s->f[g * 4 + 3][0];
        const float* mrow = &s->mus[k * MPAD];
#pragma unroll
        for (int d4 = 0; d4 < DD / 4; d4++) {
            float m0 = mrow[4 * d4 + 0];
            float m1 = mrow[4 * d4 + 1];
            float m2 = mrow[4 * d4 + 2];
            float m3 = mrow[4 * d4 + 3];
            float4 x0 = f0[d4], x1 = f1[d4], x2 = f2[d4], x3 = f3[d4];
            acc0 += m0 * x0.x + m1 * x0.y + m2 * x0.z + m3 * x0.w;
            acc1 += m0 * x1.x + m1 * x1.y + m2 * x1.z + m3 * x1.w;
            acc2 += m0 * x2.x + m1 * x2.y + m2 * x2.z + m3 * x2.w;
            acc3 += m0 * x3.x + m1 * x3.y + m2 * x3.z + m3 * x3.w;
        }
        float sk = s->kap[k] * s->invmu[k], lc = s->lc[k];
        s->L[g * 4 + 0][k] = lc + sk * s->invn[g * 4 + 0] * acc0;
        s->L[g * 4 + 1][k] = lc + sk * s->invn[g * 4 + 1] * acc1;
        s->L[g * 4 + 2][k] = lc + sk * s->invn[g * 4 + 2] * acc2;
        s->L[g * 4 + 3][k] = lc + sk * s->invn[g * 4 + 3] * acc3;
    }
    __syncthreads();

    // numer_pi[label_n][k] += ln2 - softplus(L[n,k] - L[n,label_n])
#pragma unroll
    for (int nn = 0; nn < 4; nn++) {
        int n = g * 4 + nn;
        float x = s->L[n][k] - s->L[n][s->lab[n]];
        float sp = __logf(1.0f + __expf(-fabsf(x))) + fmaxf(x, 0.0f);
        atomicAdd(&g_numer[s->lab[n] * KC + k], LN2F - sp);
    }

    // ---- arrive at grid barrier (all blocks); epilogue prework happens BEFORE the wait ----
    __threadfence();
    __syncthreads();            // also protects s->f / s->L reuse below
    if (tid == 0) atomicAdd(&g_arrive, 1);
    if (bid >= KC) return;

    // ================= epilogue prework (independent of other blocks) =================
    int i = bid;
    int*   mlist  = (int*)&s->f[0][0];        // up to 2048 ints (8KB)
    float* invn_m = &s->L[0][0];              // up to 2048 floats (8KB)
    float* ep     = &s->f[16][0];             // 8KB scratch
    float* pdmean = ep;                       // [4][128]
    float* mean_sh = ep + 512;                // 128
    float* cnts   = ep + 640;                 // 64
    float* numr   = ep + 704;                 // 64
    float (*pdm)[KC] = (float(*)[KC])(ep + 768);    // 8x64
    float (*pdu)[KC] = (float(*)[KC])(ep + 1280);   // 8x64
    float* dotm   = ep + 1792;
    float* dotu   = ep + 1856;
    float* redr   = ep + 1920;
    float* redj   = ep + 1984;

    // gather members of class i and accumulate normalized-feature mean
    int d = tid & 127, g4 = tid >> 7;
    float accm = 0.0f;
    int count_i = 0;
#pragma unroll
    for (int base = 0; base < NN; base += 2048) {
        if (tid == 0) s->cnt_sh = 0;
        __syncthreads();
#pragma unroll
        for (int r = 0; r < 4; r++) {
            int n = base + tid + 512 * r;
            int l = lab32[n << shift];
            if (l == i) { int p = atomicAdd(&s->cnt_sh, 1); mlist[p] = n; }
        }
        __syncthreads();
        int cnt = s->cnt_sh;
        count_i += cnt;
        // norms: one warp per member
        {
            int w = tid >> 5, lane = tid & 31;
            for (int m = w; m < cnt; m += 16) {
                const float4* row = (const float4*)(feat + mlist[m] * DD);
                float4 v = row[lane];
                float sq = v.x * v.x + v.y * v.y + v.z * v.z + v.w * v.w;
#pragma unroll
                for (int o = 16; o > 0; o >>= 1) sq += __shfl_xor_sync(0xffffffffu, sq, o);
                if (lane == 0) invn_m[m] = 1.0f / fmaxf(sqrtf(sq), 1e-12f);
            }
        }
        __syncthreads();
        // mean partials: group g4 handles members g4, g4+4, ...
        for (int m = g4; m < cnt; m += 4)
            accm += feat[mlist[m] * DD + d] * invn_m[m];
        __syncthreads();   // mlist/invn_m reused next chunk
    }
    pdmean[g4 * 128 + d] = accm;
    __syncthreads();

    bool zi = (count_i == 0);
    float cs = fmaxf((float)count_i, 1.0f);
    if (tid < DD) {
        float m4 = pdmean[tid] + pdmean[128 + tid] + pdmean[256 + tid] + pdmean[384 + tid];
        mean_sh[tid] = zi ? s->mus[i * MPAD + tid] * s->invmu[i] : (m4 / cs);
    }
    __syncthreads();

    // dots: thread (j = tid&63, eighth q = tid>>6), 16 d each
    {
        int j = tid & 63, q = tid >> 6;
        float dm = 0.0f, du = 0.0f;
        const float* mi = &s->mus[i * MPAD + q * 16];
        const float* mj = &s->mus[j * MPAD + q * 16];
        const float* me = &mean_sh[q * 16];
#pragma unroll
        for (int r = 0; r < 16; r++) {
            float m = mj[r];
            dm += me[r] * m;
            du += mi[r] * m;
        }
        pdm[q][j] = dm;
        pdu[q][j] = du;
    }
    __syncthreads();
    if (tid < KC) {
        float dm = 0.0f, du = 0.0f;
#pragma unroll
        for (int q = 0; q < 8; q++) { dm += pdm[q][tid]; du += pdu[q][tid]; }
        dotm[tid] = dm * s->invmu[tid];
        dotu[tid] = du * s->invmu[i] * s->invmu[tid];
    }

    // ================= grid barrier wait (prework already done) =================
    if (tid == 0) {
        volatile int* va = &g_arrive;
        while (*va < GRID) { }
    }
    __syncthreads();
    __threadfence();

    // ---- tiny post-barrier tail ----
    if (tid < KC) {
        cnts[tid] = g_counts[tid];
        numr[tid] = g_numer[i * KC + tid];
    }
    __syncthreads();
    if (tid < KC) g_numer[i * KC + tid] = 0.0f;   // self-reset own row

    if (tid < KC) {
        int j = tid;
        float diff = s->kap[i] * dotm[i] - s->kap[j] * dotm[j];
        float h = (j != i) ? fmaxf(0.5f * fabsf((float)(i - j)) - diff, 0.0f) / cs : 0.0f;
        float cnt_j = cnts[j];
        bool zp = zi || (cnt_j == 0.0f);
        float wgt = (i == j) ? 0.0f : fabsf((float)(i - j));
        float contrib;
        if (zp) {
            float ki = s->kap[i], kj = s->kap[j];
            contrib = wgt * 0.5f * (A_of(ki) * (ki - kj * dotu[j]) + A_of(kj) * (kj - ki * dotu[j]));
        } else {
            contrib = wgt * numr[j] / cs;   // symmetry-folded JS
        }
        redr[j] = h;
        redj[j] = contrib;
    }
    __syncthreads();
    if (tid < 32) {
        float r = redr[tid] + redr[tid + 32];
        float jj = redj[tid] + redj[tid + 32];
#pragma unroll
        for (int o = 16; o > 0; o >>= 1) {
            r  += __shfl_xor_sync(0xffffffffu, r, o);
            jj += __shfl_xor_sync(0xffffffffu, jj, o);
        }
        if (tid == 0) {
            atomicAdd(&g_rank, r);
            atomicAdd(&g_js, jj);
            __threadfence();
            if (atomicAdd(&g_done, 1) == KC - 1) {
                float rr = atomicAdd(&g_rank, 0.0f);
                float ss = atomicAdd(&g_js, 0.0f);
                out[0] = rr / (4096.0f + 1e-9f) + ss / (87360.0f + 1e-9f);
                for (int c = 0; c < KC; c++) g_counts[c] = 0.0f;
                g_rank = 0.0f; g_js = 0.0f; g_done = 0; g_arrive = 0;
            }
        }
    }
}

extern "C" void kernel_launch(void* const* d_in, const int* in_sizes, int n_in,
                              void* d_out, int out_size) {
    const float* features  = (const float*)d_in[0];
    const float* mus_param = (const float*)d_in[1];
    const float* rho_kappa = (const float*)d_in[2];
    const int*   labels32  = (const int*)d_in[3];
    float* out = (float*)d_out;

    cudaFuncSetAttribute(k_fused, cudaFuncAttributeMaxDynamicSharedMemorySize,
                         (int)sizeof(Smem));
    k_fused<<<GRID, NT, sizeof(Smem)>>>(features, mus_param, rho_kappa, labels32, out);
}

// round 10
// speedup vs baseline: 1.2581x; 1.2581x over previous
#include <cuda_runtime.h>
#include <cuda_bf16.h>
#include <math.h>

#define KC 64
#define DD 128
#define NN 4096
#define NB 32
#define NT 1024
#define GRID (NN / NB)   // 128 blocks: one per SM, single balanced wave
#define MPAD 129

#define LN2F 0.6931471805599453f
#define LOG2PIF 1.8378770664093453f
#define LGAMMA64F 201.00931639928152f

// ---------------- device scratch (zero-init; self-resetting each run) ----------------
__device__ float g_sums[KC * DD];
__device__ float g_counts[KC];
__device__ float g_numer[KC * KC];
__device__ float g_rank;
__device__ float g_js;
__device__ int   g_arrive;
__device__ int   g_done;

__device__ __forceinline__ float softplus_precise(float x) {
    return (x > 0.0f) ? (x + log1pf(expf(-x))) : log1pf(expf(x));
}

struct Smem {
    float mus[KC * MPAD];        // raw mus, padded (33KB)
    float f[NB][DD];             // features (16KB) — epilogue scratch later
    float L[NB][KC];             // logits (8KB)    — epilogue scratch later
    float invn[NB];
    float invmu[KC], kap[KC], lc[KC];
    float musq[16][KC];
    int   lab[NB];
};

__global__ void __launch_bounds__(NT) k_fused(const float* __restrict__ feat,
                                              const float* __restrict__ musp,
                                              const float* __restrict__ rho,
                                              const int* __restrict__ lab32,
                                              float* __restrict__ out) {
    extern __shared__ char smem_raw[];
    Smem* s = (Smem*)smem_raw;
    int tid = threadIdx.x;
    int bid = blockIdx.x;
    int n0 = bid * NB;

    // labels dtype probe (odd int32 words nonzero => int32); first 2048 words, safe both ways
    int pred = (tid < 1024) ? (lab32[2 * tid + 1] != 0) : 0;

    // load mus_param coalesced -> padded rows (2048 float4 / 1024 thr = 2 each)
    {
        const float4* msrc = (const float4*)musp;
#pragma unroll
        for (int r = 0; r < 2; r++) {
            int idx = tid + NT * r;
            float4 v = msrc[idx];
            int k = idx >> 5, d = (idx & 31) * 4;
            float* p = &s->mus[k * MPAD + d];
            p[0] = v.x; p[1] = v.y; p[2] = v.z; p[3] = v.w;
        }
    }
    // load 32x128 features (1024 float4, 1 each)
    {
        const float4* src = (const float4*)(feat + n0 * DD);
        ((float4*)&s->f[0][0])[tid] = src[tid];
    }
    int anyodd = __syncthreads_or(pred);
    int shift = anyodd ? 0 : 1;

    if (tid < NB) {
        int l = lab32[(n0 + tid) << shift];
        s->lab[tid] = min(max(l, 0), KC - 1);
    }

    // mus squared-norm partials: (k = tid&63, sixteenth q = tid>>6), 8 d each
    {
        int k = tid & 63, q = tid >> 6;
        float sm = 0.0f;
        const float* p = &s->mus[k * MPAD + q * 8];
#pragma unroll
        for (int r = 0; r < 8; r++) { float m = p[r]; sm += m * m; }
        s->musq[q][k] = sm;
    }
    // feature norms: warp w handles row w (32 warps, 32 rows)
    {
        int w = tid >> 5, lane = tid & 31;
        float sm = 0.0f;
#pragma unroll
        for (int c = 0; c < 4; c++) {
            float x = s->f[w][lane + 32 * c];
            sm += x * x;
        }
#pragma unroll
        for (int o = 16; o > 0; o >>= 1) sm += __shfl_xor_sync(0xffffffffu, sm, o);
        if (lane == 0) s->invn[w] = 1.0f / fmaxf(sqrtf(sm), 1e-12f);
    }
    __syncthreads();

    // per-class scalars
    if (tid < KC) {
        float sm = 0.0f;
#pragma unroll
        for (int q = 0; q < 16; q++) sm += s->musq[q][tid];
        s->invmu[tid] = 1.0f / fmaxf(sqrtf(sm), 1e-12f);
        float r = rho[tid];
        float kap = fmaxf(softplus_precise(r), 1e-6f);
        s->kap[tid] = kap;
        float logI = (kap < 1e-3f)
                   ? 63.0f * logf(kap * 0.5f + 1e-12f) - LGAMMA64F
                   : kap - 0.5f * logf(6.283185307179586f * kap + 1e-12f);
        s->lc[tid] = -63.0f * logf(kap + 1e-12f) - 64.0f * LOG2PIF - logI;
    }
    if (tid < NB) atomicAdd(&g_counts[s->lab[tid]], 1.0f);
    __syncthreads();

    // class sums (spread REDG): d = tid&127, eighth = tid>>7 handles 4 samples
    {
        int d = tid & 127, h = tid >> 7;
#pragma unroll
        for (int nn = 0; nn < 4; nn++) {
            int n = h * 4 + nn;
            atomicAdd(&g_sums[s->lab[n] * DD + d], s->f[n][d] * s->invn[n]);
        }
    }

    // L = logC + kappa*invmu*invn*(f . mu_raw); 16 groups x 2 samples
    int g = tid >> 6;        // 0..15
    int k = tid & 63;
    {
        float acc0 = 0.f, acc1 = 0.f;
        const float4* f0 = (const float4*)&s->f[g * 2 + 0][0];
        const float4* f1 = (const float4*)&s->f[g * 2 + 1][0];
        const float* mrow = &s->mus[k * MPAD];
#pragma unroll
        for (int d4 = 0; d4 < DD / 4; d4++) {
            float m0 = mrow[4 * d4 + 0];
            float m1 = mrow[4 * d4 + 1];
            float m2 = mrow[4 * d4 + 2];
            float m3 = mrow[4 * d4 + 3];
            float4 x0 = f0[d4], x1 = f1[d4];
            acc0 += m0 * x0.x + m1 * x0.y + m2 * x0.z + m3 * x0.w;
            acc1 += m0 * x1.x + m1 * x1.y + m2 * x1.z + m3 * x1.w;
        }
        float sk = s->kap[k] * s->invmu[k], lc = s->lc[k];
        s->L[g * 2 + 0][k] = lc + sk * s->invn[g * 2 + 0] * acc0;
        s->L[g * 2 + 1][k] = lc + sk * s->invn[g * 2 + 1] * acc1;
    }
    __syncthreads();

    // numer_pi[label_n][k] += ln2 - softplus(L[n,k] - L[n,label_n]); 2 per thread
#pragma unroll
    for (int nn = 0; nn < 2; nn++) {
        int n = g * 2 + nn;
        float x = s->L[n][k] - s->L[n][s->lab[n]];
        float sp = __logf(1.0f + __expf(-fabsf(x))) + fmaxf(x, 0.0f);
        atomicAdd(&g_numer[s->lab[n] * KC + k], LN2F - sp);
    }

    // ---------------- software grid barrier ----------------
    __threadfence();
    __syncthreads();
    if (tid == 0) atomicAdd(&g_arrive, 1);
    if (bid >= KC) return;

    if (tid == 0) {
        volatile int* va = &g_arrive;
        while (*va < GRID) { }
    }
    __syncthreads();
    __threadfence();

    // ---------------- epilogue: rank + js for row i = bid ----------------
    int i = bid;
    float* ep      = &s->f[0][0];
    float* mean_sh = ep;            // 128
    float* cnts    = ep + 128;      // 64
    float* numr    = ep + 192;      // 64
    float* dotm    = ep + 256;
    float* dotu    = ep + 320;
    float* redr    = ep + 384;
    float* redj    = ep + 448;
    float (*pdm)[KC] = (float(*)[KC])&s->L[0][0];    // 16x64
    float (*pdu)[KC] = (float(*)[KC])&s->L[16][0];   // 16x64

    if (tid < KC) {
        cnts[tid] = g_counts[tid];
        numr[tid] = g_numer[i * KC + tid];
    }
    __syncthreads();

    float cnt_i = cnts[i];
    bool zi = (cnt_i == 0.0f);
    float cs = fmaxf(cnt_i, 1.0f);
    if (tid < DD)
        mean_sh[tid] = zi ? s->mus[i * MPAD + tid] * s->invmu[i]
                          : (g_sums[i * DD + tid] / cs);
    __syncthreads();
    // self-reset rows owned by this block
    if (tid < DD) g_sums[i * DD + tid] = 0.0f;
    if (tid < KC) g_numer[i * KC + tid] = 0.0f;

    // dots: thread (j = tid&63, sixteenth q = tid>>6), 8 d each
    {
        int j = tid & 63, q = tid >> 6;
        float dm = 0.0f, du = 0.0f;
        const float* mi = &s->mus[i * MPAD + q * 8];
        const float* mj = &s->mus[j * MPAD + q * 8];
        const float* me = &mean_sh[q * 8];
#pragma unroll
        for (int r = 0; r < 8; r++) {
            float m = mj[r];
            dm += me[r] * m;
            du += mi[r] * m;
        }
        pdm[q][j] = dm;
        pdu[q][j] = du;
    }
    __syncthreads();
    if (tid < KC) {
        float dm = 0.0f, du = 0.0f;
#pragma unroll
        for (int q = 0; q < 16; q++) { dm += pdm[q][tid]; du += pdu[q][tid]; }
        dotm[tid] = dm * s->invmu[tid];
        dotu[tid] = du * s->invmu[i] * s->invmu[tid];
    }
    __syncthreads();

    if (tid < KC) {
        int j = tid;
        float diff = s->kap[i] * dotm[i] - s->kap[j] * dotm[j];
        float h = (j != i) ? fmaxf(0.5f * fabsf((float)(i - j)) - diff, 0.0f) / cs : 0.0f;
        float cnt_j = cnts[j];
        bool zp = zi || (cnt_j == 0.0f);
        float wgt = (i == j) ? 0.0f : fabsf((float)(i - j));
        float contrib;
        if (zp) {
            float ki = s->kap[i], kj = s->kap[j];
            float kci = fmaxf(ki, 1e-8f), kcj = fmaxf(kj, 1e-8f);
            float Ai = (kci > 50.0f) ? (1.0f - 127.0f / (2.0f * kci)) : (kci / 128.0f);
            float Aj = (kcj > 50.0f) ? (1.0f - 127.0f / (2.0f * kcj)) : (kcj / 128.0f);
            contrib = wgt * 0.5f * (Ai * (ki - kj * dotu[j]) + Aj * (kj - ki * dotu[j]));
        } else {
            contrib = wgt * numr[j] / cs;   // symmetry-folded JS
        }
        redr[j] = h;
        redj[j] = contrib;
    }
    __syncthreads();
    if (tid < 32) {
        float r = redr[tid] + redr[tid + 32];
        float jj = redj[tid] + redj[tid + 32];
#pragma unroll
        for (int o = 16; o > 0; o >>= 1) {
            r  += __shfl_xor_sync(0xffffffffu, r, o);
            jj += __shfl_xor_sync(0xffffffffu, jj, o);
        }
        if (tid == 0) {
            atomicAdd(&g_rank, r);
            atomicAdd(&g_js, jj);
            __threadfence();
            if (atomicAdd(&g_done, 1) == KC - 1) {
                float rr = atomicAdd(&g_rank, 0.0f);
                float ss = atomicAdd(&g_js, 0.0f);
                out[0] = rr / (4096.0f + 1e-9f) + ss / (87360.0f + 1e-9f);
                for (int c = 0; c < KC; c++) g_counts[c] = 0.0f;
                g_rank = 0.0f; g_js = 0.0f; g_done = 0; g_arrive = 0;
            }
        }
    }
}

extern "C" void kernel_launch(void* const* d_in, const int* in_sizes, int n_in,
                              void* d_out, int out_size) {
    const float* features  = (const float*)d_in[0];
    const float* mus_param = (const float*)d_in[1];
    const float* rho_kappa = (const float*)d_in[2];
    const int*   labels32  = (const int*)d_in[3];
    float* out = (float*)d_out;

    cudaFuncSetAttribute(k_fused, cudaFuncAttributeMaxDynamicSharedMemorySize,
                         (int)sizeof(Smem));
    k_fused<<<GRID, NT, sizeof(Smem)>>>(features, mus_param, rho_kappa, labels32, out);
}

// round 11
// speedup vs baseline: 1.4320x; 1.1382x over previous
#include <cuda_runtime.h>
#include <cuda_bf16.h>
#include <math.h>

#define KC 64
#define DD 128
#define NN 4096
#define NB 32
#define NT 512
#define GRID (NN / NB)   // 128 blocks: one per SM, single balanced wave
#define MPAD 129

#define LN2F 0.6931471805599453f
#define LOG2PIF 1.8378770664093453f
#define LGAMMA64F 201.00931639928152f

// ---------------- device scratch (zero-init; self-resetting each run) ----------------
__device__ __align__(16) float g_sums[KC * DD];
__device__ __align__(16) float g_numer[KC * KC];
__device__ float g_counts[KC];
__device__ float g_rank;
__device__ float g_js;
__device__ int   g_arrive;
__device__ int   g_done;

__device__ __forceinline__ float softplus_precise(float x) {
    return (x > 0.0f) ? (x + log1pf(expf(-x))) : log1pf(expf(x));
}

// log1p(t) on t in [0,1] via Taylor at t=0.5 (deg 11, |err| < 2e-7). Pure FFMA.
__device__ __forceinline__ float log1p_poly(float t) {
    float s = t - 0.5f;
    float p = -0.0017337974f + 0.0010507863f * s;   // c10 + c11*s
    p = fmaf(p, s,  0.0028896624f);
    p = fmaf(p, s, -0.0048773053f);
    p = fmaf(p, s,  0.0083610948f);
    p = fmaf(p, s, -0.0146319159f);
    p = fmaf(p, s,  0.0263374486f);
    p = fmaf(p, s, -0.0493827160f);
    p = fmaf(p, s,  0.0987654321f);
    p = fmaf(p, s, -0.2222222222f);
    p = fmaf(p, s,  0.6666666667f);
    p = fmaf(p, s,  0.4054651081f);
    return p;
}

__device__ __forceinline__ void red_v4(float* gptr, float a, float b, float c, float d) {
    unsigned long long ga = (unsigned long long)__cvta_generic_to_global(gptr);
    asm volatile("red.global.add.v4.f32 [%0], {%1, %2, %3, %4};"
                 :: "l"(ga), "f"(a), "f"(b), "f"(c), "f"(d) : "memory");
}

struct Smem {
    float mus[KC * MPAD];        // raw mus, padded (33KB)
    float f[NB][DD];             // features (16KB) — epilogue scratch later
    float L[NB][KC];             // logits (8KB)    — epilogue scratch later
    float invn[NB];
    float invmu[KC], kap[KC], lc[KC];
    float musq[8][KC];
    int   lab[NB];
};

__global__ void __launch_bounds__(NT) k_fused(const float* __restrict__ feat,
                                              const float* __restrict__ musp,
                                              const float* __restrict__ rho,
                                              const int* __restrict__ lab32,
                                              float* __restrict__ out) {
    extern __shared__ char smem_raw[];
    Smem* s = (Smem*)smem_raw;
    int tid = threadIdx.x;
    int bid = blockIdx.x;
    int n0 = bid * NB;

    // labels dtype probe (odd int32 words nonzero => int32 labels)
    int pred = (lab32[2 * tid + 1] != 0);

    // load mus_param coalesced -> padded rows
    {
        const float4* msrc = (const float4*)musp;
#pragma unroll
        for (int r = 0; r < 4; r++) {
            int idx = tid + NT * r;
            float4 v = msrc[idx];
            int k = idx >> 5, d = (idx & 31) * 4;
            float* p = &s->mus[k * MPAD + d];
            p[0] = v.x; p[1] = v.y; p[2] = v.z; p[3] = v.w;
        }
    }
    // load 32x128 features
    {
        const float4* src = (const float4*)(feat + n0 * DD);
        float4* dst = (float4*)&s->f[0][0];
        dst[tid]      = src[tid];
        dst[tid + NT] = src[tid + NT];
    }
    int anyodd = __syncthreads_or(pred);
    int shift = anyodd ? 0 : 1;

    if (tid < NB) {
        int l = lab32[(n0 + tid) << shift];
        s->lab[tid] = min(max(l, 0), KC - 1);
    }

    // mus squared-norm partials
    {
        int k = tid & 63, q = tid >> 6;
        float sm = 0.0f;
        const float* p = &s->mus[k * MPAD + q * 16];
#pragma unroll
        for (int r = 0; r < 16; r++) { float m = p[r]; sm += m * m; }
        s->musq[q][k] = sm;
    }
    // feature norms: warp w handles rows 2w, 2w+1
    {
        int w = tid >> 5, lane = tid & 31;
#pragma unroll
        for (int rr = 0; rr < 2; rr++) {
            int r = 2 * w + rr;
            float sm = 0.0f;
#pragma unroll
            for (int c = 0; c < 4; c++) {
                float x = s->f[r][lane + 32 * c];
                sm += x * x;
            }
#pragma unroll
            for (int o = 16; o > 0; o >>= 1) sm += __shfl_xor_sync(0xffffffffu, sm, o);
            if (lane == 0) s->invn[r] = 1.0f / fmaxf(sqrtf(sm), 1e-12f);
        }
    }
    __syncthreads();

    // per-class scalars
    if (tid < KC) {
        float sm = 0.0f;
#pragma unroll
        for (int q = 0; q < 8; q++) sm += s->musq[q][tid];
        s->invmu[tid] = 1.0f / fmaxf(sqrtf(sm), 1e-12f);
        float r = rho[tid];
        float kap = fmaxf(softplus_precise(r), 1e-6f);
        s->kap[tid] = kap;
        float logI = (kap < 1e-3f)
                   ? 63.0f * logf(kap * 0.5f + 1e-12f) - LGAMMA64F
                   : kap - 0.5f * logf(6.283185307179586f * kap + 1e-12f);
        s->lc[tid] = -63.0f * logf(kap + 1e-12f) - 64.0f * LOG2PIF - logI;
    }
    if (tid < NB) atomicAdd(&g_counts[s->lab[tid]], 1.0f);
    __syncthreads();

    // class sums via vector REDG: thread -> (d-quad = tid&31, 2 samples)
    {
        int q4 = (tid & 31) * 4;         // d quad start
        int nb = tid >> 5;               // 0..15
#pragma unroll
        for (int h = 0; h < 2; h++) {
            int n = nb + 16 * h;
            float iv = s->invn[n];
            const float* fr = &s->f[n][q4];
            red_v4(&g_sums[s->lab[n] * DD + q4],
                   fr[0] * iv, fr[1] * iv, fr[2] * iv, fr[3] * iv);
        }
    }

    // L = logC + kappa*invmu*invn*(f . mu_raw); 8 groups x 4 samples
    int g = tid >> 6;
    int k = tid & 63;
    {
        float acc0 = 0.f, acc1 = 0.f, acc2 = 0.f, acc3 = 0.f;
        const float4* f0 = (const float4*)&s->f[g * 4 + 0][0];
        const float4* f1 = (const float4*)&s->f[g * 4 + 1][0];
        const float4* f2 = (const float4*)&s->f[g * 4 + 2][0];
        const float4* f3 = (const float4*)&s->f[g * 4 + 3][0];
        const float* mrow = &s->mus[k * MPAD];
#pragma unroll
        for (int d4 = 0; d4 < DD / 4; d4++) {
            float m0 = mrow[4 * d4 + 0];
            float m1 = mrow[4 * d4 + 1];
            float m2 = mrow[4 * d4 + 2];
            float m3 = mrow[4 * d4 + 3];
            float4 x0 = f0[d4], x1 = f1[d4], x2 = f2[d4], x3 = f3[d4];
            acc0 += m0 * x0.x + m1 * x0.y + m2 * x0.z + m3 * x0.w;
            acc1 += m0 * x1.x + m1 * x1.y + m2 * x1.z + m3 * x1.w;
            acc2 += m0 * x2.x + m1 * x2.y + m2 * x2.z + m3 * x2.w;
            acc3 += m0 * x3.x + m1 * x3.y + m2 * x3.z + m3 * x3.w;
        }
        float sk = s->kap[k] * s->invmu[k], lc = s->lc[k];
        s->L[g * 4 + 0][k] = lc + sk * s->invn[g * 4 + 0] * acc0;
        s->L[g * 4 + 1][k] = lc + sk * s->invn[g * 4 + 1] * acc1;
        s->L[g * 4 + 2][k] = lc + sk * s->invn[g * 4 + 2] * acc2;
        s->L[g * 4 + 3][k] = lc + sk * s->invn[g * 4 + 3] * acc3;
    }
    __syncthreads();

    // numer: thread -> (n = tid>>4, k-quad = (tid&15)*4); poly softplus, one v4 REDG
    {
        int n = tid >> 4;
        int k0 = (tid & 15) * 4;
        float Li = s->L[n][s->lab[n]];
        float v[4];
#pragma unroll
        for (int c = 0; c < 4; c++) {
            float x = s->L[n][k0 + c] - Li;
            float t = __expf(-fabsf(x));
            float sp = log1p_poly(t) + fmaxf(x, 0.0f);
            v[c] = LN2F - sp;
        }
        red_v4(&g_numer[s->lab[n] * KC + k0], v[0], v[1], v[2], v[3]);
    }

    // ---------------- software grid barrier ----------------
    __threadfence();
    __syncthreads();
    if (tid == 0) atomicAdd(&g_arrive, 1);
    if (bid >= KC) return;

    if (tid == 0) {
        volatile int* va = &g_arrive;
        while (*va < GRID) { }
    }
    __syncthreads();
    __threadfence();

    // ---------------- epilogue: rank + js for row i = bid ----------------
    int i = bid;
    float* ep      = &s->f[0][0];
    float* mean_sh = ep;            // 128
    float* cnts    = ep + 128;      // 64
    float* numr    = ep + 192;      // 64
    float* dotm    = ep + 256;
    float* dotu    = ep + 320;
    float* redr    = ep + 384;
    float* redj    = ep + 448;
    float (*pdm)[KC] = (float(*)[KC])&s->L[0][0];    // 8x64
    float (*pdu)[KC] = (float(*)[KC])&s->L[8][0];    // 8x64

    if (tid < KC) {
        cnts[tid] = g_counts[tid];
        numr[tid] = g_numer[i * KC + tid];
    }
    __syncthreads();

    float cnt_i = cnts[i];
    bool zi = (cnt_i == 0.0f);
    float cs = fmaxf(cnt_i, 1.0f);
    if (tid < DD)
        mean_sh[tid] = zi ? s->mus[i * MPAD + tid] * s->invmu[i]
                          : (g_sums[i * DD + tid] / cs);
    __syncthreads();
    // self-reset rows owned by this block
    if (tid < DD) g_sums[i * DD + tid] = 0.0f;
    if (tid < KC) g_numer[i * KC + tid] = 0.0f;

    // dots: thread (j = tid&63, eighth q = tid>>6), 16 d each
    {
        int j = tid & 63, q = tid >> 6;
        float dm = 0.0f, du = 0.0f;
        const float* mi = &s->mus[i * MPAD + q * 16];
        const float* mj = &s->mus[j * MPAD + q * 16];
        const float* me = &mean_sh[q * 16];
#pragma unroll
        for (int r = 0; r < 16; r++) {
            float m = mj[r];
            dm += me[r] * m;
            du += mi[r] * m;
        }
        pdm[q][j] = dm;
        pdu[q][j] = du;
    }
    __syncthreads();
    if (tid < KC) {
        float dm = 0.0f, du = 0.0f;
#pragma unroll
        for (int q = 0; q < 8; q++) { dm += pdm[q][tid]; du += pdu[q][tid]; }
        dotm[tid] = dm * s->invmu[tid];
        dotu[tid] = du * s->invmu[i] * s->invmu[tid];
    }
    __syncthreads();

    if (tid < KC) {
        int j = tid;
        float diff = s->kap[i] * dotm[i] - s->kap[j] * dotm[j];
        float h = (j != i) ? fmaxf(0.5f * fabsf((float)(i - j)) - diff, 0.0f) / cs : 0.0f;
        float cnt_j = cnts[j];
        bool zp = zi || (cnt_j == 0.0f);
        float wgt = (i == j) ? 0.0f : fabsf((float)(i - j));
        float contrib;
        if (zp) {
            float ki = s->kap[i], kj = s->kap[j];
            float kci = fmaxf(ki, 1e-8f), kcj = fmaxf(kj, 1e-8f);
            float Ai = (kci > 50.0f) ? (1.0f - 127.0f / (2.0f * kci)) : (kci / 128.0f);
            float Aj = (kcj > 50.0f) ? (1.0f - 127.0f / (2.0f * kcj)) : (kcj / 128.0f);
            contrib = wgt * 0.5f * (Ai * (ki - kj * dotu[j]) + Aj * (kj - ki * dotu[j]));
        } else {
            contrib = wgt * numr[j] / cs;   // symmetry-folded JS
        }
        redr[j] = h;
        redj[j] = contrib;
    }
    __syncthreads();
    if (tid < 32) {
        float r = redr[tid] + redr[tid + 32];
        float jj = redj[tid] + redj[tid + 32];
#pragma unroll
        for (int o = 16; o > 0; o >>= 1) {
            r  += __shfl_xor_sync(0xffffffffu, r, o);
            jj += __shfl_xor_sync(0xffffffffu, jj, o);
        }
        if (tid == 0) {
            atomicAdd(&g_rank, r);
            atomicAdd(&g_js, jj);
            __threadfence();
            if (atomicAdd(&g_done, 1) == KC - 1) {
                float rr = atomicAdd(&g_rank, 0.0f);
                float ss = atomicAdd(&g_js, 0.0f);
                out[0] = rr / (4096.0f + 1e-9f) + ss / (87360.0f + 1e-9f);
                for (int c = 0; c < KC; c++) g_counts[c] = 0.0f;
                g_rank = 0.0f; g_js = 0.0f; g_done = 0; g_arrive = 0;
            }
        }
    }
}

extern "C" void kernel_launch(void* const* d_in, const int* in_sizes, int n_in,
                              void* d_out, int out_size) {
    const float* features  = (const float*)d_in[0];
    const float* mus_param = (const float*)d_in[1];
    const float* rho_kappa = (const float*)d_in[2];
    const int*   labels32  = (const int*)d_in[3];
    float* out = (float*)d_out;

    cudaFuncSetAttribute(k_fused, cudaFuncAttributeMaxDynamicSharedMemorySize,
                         (int)sizeof(Smem));
    k_fused<<<GRID, NT, sizeof(Smem)>>>(features, mus_param, rho_kappa, labels32, out);
}